// round 8
// baseline (speedup 1.0000x reference)
#include <cuda_runtime.h>
#include <cstdint>

// ---------------------------------------------------------------- dims
#define T_STEPS 32
#define B_DIM   256
#define F_DIM   2048
#define H_DIM   4096
#define M_DIM   (T_STEPS * B_DIM)   // 8192
#define K_DIM   F_DIM               // 2048
#define N_DIM   H_DIM               // 4096
#define BH      (B_DIM * H_DIM)     // 1048576

// ---------------------------------------------------------------- fused GEMM + LIF
// C[M,N] = A[M,K] @ W[N,K]^T + bias[N], rows permuted row' = b*32 + t so a
// 128-row tile contains 4 complete T-scans. Epilogue runs the LIF scan
// in-CTA and writes spikes + counts directly (no g_cur scratch at all).
// Numerics: fma.rn, k ascending, one accumulator, one bias add, LIF ops
// identical to rounds 1/5 -> bit-exact with reference (rel_err 0.0).
#define BM   128
#define BN   256
#define BK   16
#define ASTR 132                       // floats per k-row of A tile (+pad)
#define BSTR 260                       // floats per k-row of B tile (+pad)
#define AS_FLOATS (2 * BK * ASTR)      // 4224
#define BS_FLOATS (2 * BK * BSTR)      // 8320
#define SMEM_DYN  ((AS_FLOATS + BS_FLOATS) * 4)   // 50176 bytes

__global__ __launch_bounds__(256, 1)
void gemm_lif_fused(const float* __restrict__ A,
                    const float* __restrict__ W,
                    const float* __restrict__ bias,
                    float* __restrict__ out)
{
    extern __shared__ float sm[];
    float* As = sm;                    // [2][BK][ASTR]
    float* Bs = sm + AS_FLOATS;        // [2][BK][BSTR]

    const int tid = threadIdx.x;
    const int tx  = tid & 15;          // N direction (16 cols each)
    const int ty  = tid >> 4;          // M direction (8 rows each)

    const int rowBase = blockIdx.y * BM;   // permuted row space
    const int colBase = blockIdx.x * BN;

    // loader indices: rA = tid>>2 handles rows rA and rA+64; kq = 4 k's
    const int rA = tid >> 2;               // 0..63
    const int kq = (tid & 3) << 2;         // 0,4,8,12

    // A rows, permuted: r' = rowBase + r ; global row = (r'&31)*256 + (r'>>5)
    const int rp0 = rowBase + rA;
    const int rp1 = rowBase + rA + 64;
    const float* aP0 = A + (size_t)(((rp0 & 31) << 8) + (rp0 >> 5)) * K_DIM + kq;
    const float* aP1 = A + (size_t)(((rp1 & 31) << 8) + (rp1 >> 5)) * K_DIM + kq;
    // W rows: colBase + rA + {0,64,128,192}
    const float* wP0 = W + (size_t)(colBase + rA +   0) * K_DIM + kq;
    const float* wP1 = W + (size_t)(colBase + rA +  64) * K_DIM + kq;
    const float* wP2 = W + (size_t)(colBase + rA + 128) * K_DIM + kq;
    const float* wP3 = W + (size_t)(colBase + rA + 192) * K_DIM + kq;

    float acc[8][16];
#pragma unroll
    for (int i = 0; i < 8; i++)
#pragma unroll
        for (int j = 0; j < 16; j++) acc[i][j] = 0.0f;

    // prologue: chunk 0 -> buffer 0
    float4 a0 = *(const float4*)(aP0);
    float4 a1 = *(const float4*)(aP1);
    float4 w0 = *(const float4*)(wP0);
    float4 w1 = *(const float4*)(wP1);
    float4 w2 = *(const float4*)(wP2);
    float4 w3 = *(const float4*)(wP3);
#pragma unroll
    for (int q = 0; q < 4; q++) {
        float va[4] = {a0.x, a0.y, a0.z, a0.w};
        // (unrolled below; q indexes k offset)
    }
    {
        As[(kq + 0) * ASTR + rA] = a0.x; As[(kq + 1) * ASTR + rA] = a0.y;
        As[(kq + 2) * ASTR + rA] = a0.z; As[(kq + 3) * ASTR + rA] = a0.w;
        As[(kq + 0) * ASTR + rA + 64] = a1.x; As[(kq + 1) * ASTR + rA + 64] = a1.y;
        As[(kq + 2) * ASTR + rA + 64] = a1.z; As[(kq + 3) * ASTR + rA + 64] = a1.w;
        Bs[(kq + 0) * BSTR + rA +   0] = w0.x; Bs[(kq + 1) * BSTR + rA +   0] = w0.y;
        Bs[(kq + 2) * BSTR + rA +   0] = w0.z; Bs[(kq + 3) * BSTR + rA +   0] = w0.w;
        Bs[(kq + 0) * BSTR + rA +  64] = w1.x; Bs[(kq + 1) * BSTR + rA +  64] = w1.y;
        Bs[(kq + 2) * BSTR + rA +  64] = w1.z; Bs[(kq + 3) * BSTR + rA +  64] = w1.w;
        Bs[(kq + 0) * BSTR + rA + 128] = w2.x; Bs[(kq + 1) * BSTR + rA + 128] = w2.y;
        Bs[(kq + 2) * BSTR + rA + 128] = w2.z; Bs[(kq + 3) * BSTR + rA + 128] = w2.w;
        Bs[(kq + 0) * BSTR + rA + 192] = w3.x; Bs[(kq + 1) * BSTR + rA + 192] = w3.y;
        Bs[(kq + 2) * BSTR + rA + 192] = w3.z; Bs[(kq + 3) * BSTR + rA + 192] = w3.w;
    }
    __syncthreads();

    const int NIT = K_DIM / BK;   // 128
    for (int it = 0; it < NIT; it++) {
        const int cur = it & 1;
        const int nxt = cur ^ 1;

        if (it + 1 < NIT) {
            const size_t off = (size_t)(it + 1) * BK;
            a0 = *(const float4*)(aP0 + off);
            a1 = *(const float4*)(aP1 + off);
            w0 = *(const float4*)(wP0 + off);
            w1 = *(const float4*)(wP1 + off);
            w2 = *(const float4*)(wP2 + off);
            w3 = *(const float4*)(wP3 + off);
        }

        const float* Ab = As + cur * BK * ASTR;
        const float* Bb = Bs + cur * BK * BSTR;
#pragma unroll
        for (int k = 0; k < BK; k++) {
            float a[8], b[16];
            float4 t0 = *(const float4*)(Ab + k * ASTR + ty * 8);
            float4 t1 = *(const float4*)(Ab + k * ASTR + ty * 8 + 4);
            a[0] = t0.x; a[1] = t0.y; a[2] = t0.z; a[3] = t0.w;
            a[4] = t1.x; a[5] = t1.y; a[6] = t1.z; a[7] = t1.w;
            float4 u0 = *(const float4*)(Bb + k * BSTR + tx * 16);
            float4 u1 = *(const float4*)(Bb + k * BSTR + tx * 16 + 4);
            float4 u2 = *(const float4*)(Bb + k * BSTR + tx * 16 + 8);
            float4 u3 = *(const float4*)(Bb + k * BSTR + tx * 16 + 12);
            b[0] = u0.x; b[1] = u0.y; b[2]  = u0.z; b[3]  = u0.w;
            b[4] = u1.x; b[5] = u1.y; b[6]  = u1.z; b[7]  = u1.w;
            b[8] = u2.x; b[9] = u2.y; b[10] = u2.z; b[11] = u2.w;
            b[12] = u3.x; b[13] = u3.y; b[14] = u3.z; b[15] = u3.w;
#pragma unroll
            for (int i = 0; i < 8; i++)
#pragma unroll
                for (int j = 0; j < 16; j++)
                    acc[i][j] = fmaf(a[i], b[j], acc[i][j]);
        }

        if (it + 1 < NIT) {
            float* An = As + nxt * BK * ASTR;
            float* Bn = Bs + nxt * BK * BSTR;
            An[(kq + 0) * ASTR + rA] = a0.x; An[(kq + 1) * ASTR + rA] = a0.y;
            An[(kq + 2) * ASTR + rA] = a0.z; An[(kq + 3) * ASTR + rA] = a0.w;
            An[(kq + 0) * ASTR + rA + 64] = a1.x; An[(kq + 1) * ASTR + rA + 64] = a1.y;
            An[(kq + 2) * ASTR + rA + 64] = a1.z; An[(kq + 3) * ASTR + rA + 64] = a1.w;
            Bn[(kq + 0) * BSTR + rA +   0] = w0.x; Bn[(kq + 1) * BSTR + rA +   0] = w0.y;
            Bn[(kq + 2) * BSTR + rA +   0] = w0.z; Bn[(kq + 3) * BSTR + rA +   0] = w0.w;
            Bn[(kq + 0) * BSTR + rA +  64] = w1.x; Bn[(kq + 1) * BSTR + rA +  64] = w1.y;
            Bn[(kq + 2) * BSTR + rA +  64] = w1.z; Bn[(kq + 3) * BSTR + rA +  64] = w1.w;
            Bn[(kq + 0) * BSTR + rA + 128] = w2.x; Bn[(kq + 1) * BSTR + rA + 128] = w2.y;
            Bn[(kq + 2) * BSTR + rA + 128] = w2.z; Bn[(kq + 3) * BSTR + rA + 128] = w2.w;
            Bn[(kq + 0) * BSTR + rA + 192] = w3.x; Bn[(kq + 1) * BSTR + rA + 192] = w3.y;
            Bn[(kq + 2) * BSTR + rA + 192] = w3.z; Bn[(kq + 3) * BSTR + rA + 192] = w3.w;
        }
        __syncthreads();
    }

    // ---------------- fused epilogue: bias + LIF scan, 4 b-chunks ----------
    // bias for this thread's 16 columns (added once per element, as before)
    float bb[16];
    {
        const float* bp = bias + colBase + tx * 16;
        float4 q0 = *(const float4*)(bp + 0);
        float4 q1 = *(const float4*)(bp + 4);
        float4 q2 = *(const float4*)(bp + 8);
        float4 q3 = *(const float4*)(bp + 12);
        bb[0] = q0.x; bb[1] = q0.y; bb[2]  = q0.z; bb[3]  = q0.w;
        bb[4] = q1.x; bb[5] = q1.y; bb[6]  = q1.z; bb[7]  = q1.w;
        bb[8] = q2.x; bb[9] = q2.y; bb[10] = q2.z; bb[11] = q2.w;
        bb[12] = q3.x; bb[13] = q3.y; bb[14] = q3.z; bb[15] = q3.w;
    }

    float* Cs = sm;   // reuse: 32 x BSTR floats = 33280 B <= 50176 B

#pragma unroll 1
    for (int bc = 0; bc < 4; bc++) {
        // threads owning rows [32*bc, 32*bc+32) stage C+bias into smem
        if ((ty >> 2) == bc) {
            const int rloc = (ty & 3) * 8;
#pragma unroll
            for (int i = 0; i < 8; i++) {
                float* cp = Cs + (rloc + i) * BSTR + tx * 16;
#pragma unroll
                for (int j4 = 0; j4 < 4; j4++) {
                    float4 v;
                    v.x = acc[i][j4 * 4 + 0] + bb[j4 * 4 + 0];
                    v.y = acc[i][j4 * 4 + 1] + bb[j4 * 4 + 1];
                    v.z = acc[i][j4 * 4 + 2] + bb[j4 * 4 + 2];
                    v.w = acc[i][j4 * 4 + 3] + bb[j4 * 4 + 3];
                    *(float4*)(cp + j4 * 4) = v;
                }
            }
        }
        __syncthreads();

        // all 256 threads: LIF scan over t for one column
        {
            const int col = tid;
            const int bG  = blockIdx.y * 4 + bc;
            float* ob = out + (size_t)bG * H_DIM + colBase + col;
            float v = 0.0f, cnt = 0.0f;
#pragma unroll
            for (int t = 0; t < T_STEPS; t++) {
                float x = Cs[t * BSTR + col];
                v = __fadd_rn(v, __fmul_rn(__fsub_rn(x, v), 0.5f));
                bool fire = (v >= 1.0f);
                float s = fire ? 1.0f : 0.0f;
                ob[(size_t)t * BH] = s;
                cnt += s;
                v = fire ? 0.0f : v;
            }
            ob[(size_t)T_STEPS * BH] = cnt;   // count block after spk_seq
        }
        __syncthreads();
    }
}

// ---------------------------------------------------------------- launch
extern "C" void kernel_launch(void* const* d_in, const int* in_sizes, int n_in,
                              void* d_out, int out_size)
{
    const float* x_seq = (const float*)d_in[0];  // [T,B,F]
    const float* W     = (const float*)d_in[1];  // [H,F]
    const float* b     = (const float*)d_in[2];  // [H]
    float* out = (float*)d_out;

    cudaFuncSetAttribute(gemm_lif_fused,
                         cudaFuncAttributeMaxDynamicSharedMemorySize, SMEM_DYN);

    dim3 gg(N_DIM / BN, M_DIM / BM);   // (16, 64)
    gemm_lif_fused<<<gg, 256, SMEM_DYN>>>(x_seq, W, b, out);
}

// round 9
// speedup vs baseline: 1.5584x; 1.5584x over previous
#include <cuda_runtime.h>
#include <cstdint>

// ---------------------------------------------------------------- dims
#define T_STEPS 32
#define B_DIM   256
#define F_DIM   2048
#define H_DIM   4096
#define M_DIM   (T_STEPS * B_DIM)   // 8192
#define K_DIM   F_DIM               // 2048
#define N_DIM   H_DIM               // 4096
#define BH      (B_DIM * H_DIM)     // 1048576

// ---------------------------------------------------------------- fused GEMM + LIF
// Mainloop is EXACTLY the round-5 kernel (128x128 tile, BK=16, 8x8 micro-
// tile, register-staged double buffer, 2 CTAs/SM). Rows are permuted
// row' = b*32 + t so each tile holds 4 complete T-scans; the epilogue
// stages C+bias in (reused) smem, runs the LIF scan in-CTA, and writes
// spikes + counts straight to out. No g_cur scratch, no second kernel.
// Numerics: fma.rn k-ascending single accumulator, one bias add, LIF ops
// identical to rounds 1/5 -> bit-exact (rel_err 0.0).
#define BM  128
#define BN  128
#define BK  16
#define PAD 4
#define STR (BM + PAD)   // 132

__global__ __launch_bounds__(256, 2)
void gemm_lif_fused(const float* __restrict__ A,
                    const float* __restrict__ W,
                    const float* __restrict__ bias,
                    float* __restrict__ out)
{
    __shared__ __align__(16) float As[2][BK][STR];
    __shared__ __align__(16) float Bs[2][BK][STR];

    const int tid = threadIdx.x;
    const int tx  = tid & 15;    // N direction
    const int ty  = tid >> 4;    // M direction

    const int rowBase = blockIdx.y * BM;   // permuted row space
    const int colBase = blockIdx.x * BN;

    // loader indices
    const int r0 = tid >> 2;          // 0..63
    const int r1 = r0 + 64;           // 64..127
    const int kq = (tid & 3) << 2;    // 0,4,8,12

    // permuted A rows: local r -> global row (( (rowBase+r)&31 )*256 + ((rowBase+r)>>5))
    const int rp0 = rowBase + r0;
    const int rp1 = rowBase + r1;
    const float* ApA = A + (size_t)(((rp0 & 31) << 8) + (rp0 >> 5)) * K_DIM + kq;
    const float* ApB = A + (size_t)(((rp1 & 31) << 8) + (rp1 >> 5)) * K_DIM + kq;
    const float* WpA = W + (size_t)(colBase + r0) * K_DIM + kq;
    const float* WpB = W + (size_t)(colBase + r1) * K_DIM + kq;

    float acc[8][8];
#pragma unroll
    for (int i = 0; i < 8; i++)
#pragma unroll
        for (int j = 0; j < 8; j++) acc[i][j] = 0.0f;

    // prologue: LDG chunk 0, STS into buf 0
    float4 av0 = *(const float4*)(ApA);
    float4 av1 = *(const float4*)(ApB);
    float4 bv0 = *(const float4*)(WpA);
    float4 bv1 = *(const float4*)(WpB);
    {
        As[0][kq + 0][r0] = av0.x; As[0][kq + 1][r0] = av0.y;
        As[0][kq + 2][r0] = av0.z; As[0][kq + 3][r0] = av0.w;
        As[0][kq + 0][r1] = av1.x; As[0][kq + 1][r1] = av1.y;
        As[0][kq + 2][r1] = av1.z; As[0][kq + 3][r1] = av1.w;
        Bs[0][kq + 0][r0] = bv0.x; Bs[0][kq + 1][r0] = bv0.y;
        Bs[0][kq + 2][r0] = bv0.z; Bs[0][kq + 3][r0] = bv0.w;
        Bs[0][kq + 0][r1] = bv1.x; Bs[0][kq + 1][r1] = bv1.y;
        Bs[0][kq + 2][r1] = bv1.z; Bs[0][kq + 3][r1] = bv1.w;
    }
    __syncthreads();

    const int NIT = K_DIM / BK;   // 128
    for (int it = 0; it < NIT; it++) {
        const int cur = it & 1;
        const int nxt = cur ^ 1;

        if (it + 1 < NIT) {
            const size_t off = (size_t)(it + 1) * BK;
            av0 = *(const float4*)(ApA + off);
            av1 = *(const float4*)(ApB + off);
            bv0 = *(const float4*)(WpA + off);
            bv1 = *(const float4*)(WpB + off);
        }

#pragma unroll
        for (int k = 0; k < BK; k++) {
            float a[8], b[8];
            float4 t0 = *(const float4*)&As[cur][k][ty * 8];
            float4 t1 = *(const float4*)&As[cur][k][ty * 8 + 4];
            a[0] = t0.x; a[1] = t0.y; a[2] = t0.z; a[3] = t0.w;
            a[4] = t1.x; a[5] = t1.y; a[6] = t1.z; a[7] = t1.w;
            float4 u0 = *(const float4*)&Bs[cur][k][tx * 8];
            float4 u1 = *(const float4*)&Bs[cur][k][tx * 8 + 4];
            b[0] = u0.x; b[1] = u0.y; b[2] = u0.z; b[3] = u0.w;
            b[4] = u1.x; b[5] = u1.y; b[6] = u1.z; b[7] = u1.w;
#pragma unroll
            for (int ii = 0; ii < 8; ii++)
#pragma unroll
                for (int jj = 0; jj < 8; jj++)
                    acc[ii][jj] = fmaf(a[ii], b[jj], acc[ii][jj]);
        }

        if (it + 1 < NIT) {
            As[nxt][kq + 0][r0] = av0.x; As[nxt][kq + 1][r0] = av0.y;
            As[nxt][kq + 2][r0] = av0.z; As[nxt][kq + 3][r0] = av0.w;
            As[nxt][kq + 0][r1] = av1.x; As[nxt][kq + 1][r1] = av1.y;
            As[nxt][kq + 2][r1] = av1.z; As[nxt][kq + 3][r1] = av1.w;
            Bs[nxt][kq + 0][r0] = bv0.x; Bs[nxt][kq + 1][r0] = bv0.y;
            Bs[nxt][kq + 2][r0] = bv0.z; Bs[nxt][kq + 3][r0] = bv0.w;
            Bs[nxt][kq + 0][r1] = bv1.x; Bs[nxt][kq + 1][r1] = bv1.y;
            Bs[nxt][kq + 2][r1] = bv1.z; Bs[nxt][kq + 3][r1] = bv1.w;
        }
        __syncthreads();
    }

    // ---------------- fused epilogue: bias + LIF scan -----------------------
    // bias for this thread's 8 columns (single add per element, as before)
    float bb[8];
    {
        const float* bp = bias + colBase + tx * 8;
        float4 q0 = *(const float4*)(bp + 0);
        float4 q1 = *(const float4*)(bp + 4);
        bb[0] = q0.x; bb[1] = q0.y; bb[2] = q0.z; bb[3] = q0.w;
        bb[4] = q1.x; bb[5] = q1.y; bb[6] = q1.z; bb[7] = q1.w;
    }

    // reuse As+Bs (contiguous, 2*2*16*132*4 = 33792 B) as Cs[64][STR]
    float* Cs = &As[0][0][0];   // 64*132*4 = 33792 B exactly

#pragma unroll 1
    for (int half = 0; half < 2; half++) {
        // threads owning rows [64*half, 64*half+64) stage C+bias into smem
        if ((ty >> 3) == half) {
            const int rloc = (ty & 7) * 8;
#pragma unroll
            for (int i = 0; i < 8; i++) {
                float* cp = Cs + (rloc + i) * STR + tx * 8;
                float4 v0, v1;
                v0.x = acc[i][0] + bb[0];
                v0.y = acc[i][1] + bb[1];
                v0.z = acc[i][2] + bb[2];
                v0.w = acc[i][3] + bb[3];
                v1.x = acc[i][4] + bb[4];
                v1.y = acc[i][5] + bb[5];
                v1.z = acc[i][6] + bb[6];
                v1.w = acc[i][7] + bb[7];
                *(float4*)(cp + 0) = v0;
                *(float4*)(cp + 4) = v1;
            }
        }
        __syncthreads();

        // 256 threads: 2 b-chunks x 128 columns, one LIF scan each
        {
            const int blocal = tid >> 7;          // 0..1
            const int col    = tid & 127;         // 0..127
            const int bG     = blockIdx.y * 4 + half * 2 + blocal;
            float* ob = out + (size_t)bG * H_DIM + colBase + col;
            const float* cs = Cs + (blocal * 32) * STR + col;
            float v = 0.0f, cnt = 0.0f;
#pragma unroll
            for (int t = 0; t < T_STEPS; t++) {
                float x = cs[t * STR];
                v = __fadd_rn(v, __fmul_rn(__fsub_rn(x, v), 0.5f));
                bool fire = (v >= 1.0f);
                float s = fire ? 1.0f : 0.0f;
                ob[(size_t)t * BH] = s;
                cnt += s;
                v = fire ? 0.0f : v;
            }
            ob[(size_t)T_STEPS * BH] = cnt;       // count block after spk_seq
        }
        __syncthreads();
    }
}

// ---------------------------------------------------------------- launch
extern "C" void kernel_launch(void* const* d_in, const int* in_sizes, int n_in,
                              void* d_out, int out_size)
{
    const float* x_seq = (const float*)d_in[0];  // [T,B,F]
    const float* W     = (const float*)d_in[1];  // [H,F]
    const float* b     = (const float*)d_in[2];  // [H]
    float* out = (float*)d_out;

    dim3 gg(N_DIM / BN, M_DIM / BM);   // (32, 64)
    gemm_lif_fused<<<gg, 256>>>(x_seq, W, b, out);
}

// round 10
// speedup vs baseline: 1.5908x; 1.0208x over previous
#include <cuda_runtime.h>
#include <cstdint>

// ---------------------------------------------------------------- dims
#define T_STEPS 32
#define B_DIM   256
#define F_DIM   2048
#define H_DIM   4096
#define M_DIM   (T_STEPS * B_DIM)   // 8192
#define K_DIM   F_DIM               // 2048
#define N_DIM   H_DIM               // 4096
#define BH      (B_DIM * H_DIM)     // 1048576

// ---------------------------------------------------------------- fused GEMM + LIF
// Round-9 winner with ONE change: warp lane mapping is now 8 rows x 4 cols
// (warp tile 64x32, CTA = 2x4 warps) instead of 2x16. This cuts unique
// smem operand bytes per warp per k from 576 B to 384 B (-33% LDS
// wavefronts; L1 pipe was at 95.2%). Per-element fp32 op sequence is
// unchanged -> bit-exact with reference (rel_err 0.0).
#define BM  128
#define BN  128
#define BK  16
#define PAD 4
#define STR (BM + PAD)   // 132

__global__ __launch_bounds__(256, 2)
void gemm_lif_fused(const float* __restrict__ A,
                    const float* __restrict__ W,
                    const float* __restrict__ bias,
                    float* __restrict__ out)
{
    __shared__ __align__(16) float As[2][BK][STR];
    __shared__ __align__(16) float Bs[2][BK][STR];

    const int tid  = threadIdx.x;
    const int lane = tid & 31;
    const int wid  = tid >> 5;
    const int wm   = wid >> 2;            // 0..1 warp row (64 rows each)
    const int wn   = wid & 3;             // 0..3 warp col (32 cols each)
    const int lr   = lane >> 2;           // 0..7 lane row (8 rows each)
    const int lc   = lane & 3;            // 0..3 lane col (8 cols each)

    const int aRow = wm * 64 + lr * 8;    // this thread's 8 rows in tile
    const int bCol = wn * 32 + lc * 8;    // this thread's 8 cols in tile

    const int rowBase = blockIdx.y * BM;  // permuted row space
    const int colBase = blockIdx.x * BN;

    // loader indices (unchanged)
    const int r0 = tid >> 2;          // 0..63
    const int r1 = r0 + 64;           // 64..127
    const int kq = (tid & 3) << 2;    // 0,4,8,12

    // permuted A rows: local r -> global row ((r'&31)*256 + (r'>>5))
    const int rp0 = rowBase + r0;
    const int rp1 = rowBase + r1;
    const float* ApA = A + (size_t)(((rp0 & 31) << 8) + (rp0 >> 5)) * K_DIM + kq;
    const float* ApB = A + (size_t)(((rp1 & 31) << 8) + (rp1 >> 5)) * K_DIM + kq;
    const float* WpA = W + (size_t)(colBase + r0) * K_DIM + kq;
    const float* WpB = W + (size_t)(colBase + r1) * K_DIM + kq;

    float acc[8][8];
#pragma unroll
    for (int i = 0; i < 8; i++)
#pragma unroll
        for (int j = 0; j < 8; j++) acc[i][j] = 0.0f;

    // prologue: LDG chunk 0, STS into buf 0
    float4 av0 = *(const float4*)(ApA);
    float4 av1 = *(const float4*)(ApB);
    float4 bv0 = *(const float4*)(WpA);
    float4 bv1 = *(const float4*)(WpB);
    {
        As[0][kq + 0][r0] = av0.x; As[0][kq + 1][r0] = av0.y;
        As[0][kq + 2][r0] = av0.z; As[0][kq + 3][r0] = av0.w;
        As[0][kq + 0][r1] = av1.x; As[0][kq + 1][r1] = av1.y;
        As[0][kq + 2][r1] = av1.z; As[0][kq + 3][r1] = av1.w;
        Bs[0][kq + 0][r0] = bv0.x; Bs[0][kq + 1][r0] = bv0.y;
        Bs[0][kq + 2][r0] = bv0.z; Bs[0][kq + 3][r0] = bv0.w;
        Bs[0][kq + 0][r1] = bv1.x; Bs[0][kq + 1][r1] = bv1.y;
        Bs[0][kq + 2][r1] = bv1.z; Bs[0][kq + 3][r1] = bv1.w;
    }
    __syncthreads();

    const int NIT = K_DIM / BK;   // 128
    for (int it = 0; it < NIT; it++) {
        const int cur = it & 1;
        const int nxt = cur ^ 1;

        if (it + 1 < NIT) {
            const size_t off = (size_t)(it + 1) * BK;
            av0 = *(const float4*)(ApA + off);
            av1 = *(const float4*)(ApB + off);
            bv0 = *(const float4*)(WpA + off);
            bv1 = *(const float4*)(WpB + off);
        }

#pragma unroll
        for (int k = 0; k < BK; k++) {
            float a[8], b[8];
            float4 t0 = *(const float4*)&As[cur][k][aRow];
            float4 t1 = *(const float4*)&As[cur][k][aRow + 4];
            a[0] = t0.x; a[1] = t0.y; a[2] = t0.z; a[3] = t0.w;
            a[4] = t1.x; a[5] = t1.y; a[6] = t1.z; a[7] = t1.w;
            float4 u0 = *(const float4*)&Bs[cur][k][bCol];
            float4 u1 = *(const float4*)&Bs[cur][k][bCol + 4];
            b[0] = u0.x; b[1] = u0.y; b[2] = u0.z; b[3] = u0.w;
            b[4] = u1.x; b[5] = u1.y; b[6] = u1.z; b[7] = u1.w;
#pragma unroll
            for (int ii = 0; ii < 8; ii++)
#pragma unroll
                for (int jj = 0; jj < 8; jj++)
                    acc[ii][jj] = fmaf(a[ii], b[jj], acc[ii][jj]);
        }

        if (it + 1 < NIT) {
            As[nxt][kq + 0][r0] = av0.x; As[nxt][kq + 1][r0] = av0.y;
            As[nxt][kq + 2][r0] = av0.z; As[nxt][kq + 3][r0] = av0.w;
            As[nxt][kq + 0][r1] = av1.x; As[nxt][kq + 1][r1] = av1.y;
            As[nxt][kq + 2][r1] = av1.z; As[nxt][kq + 3][r1] = av1.w;
            Bs[nxt][kq + 0][r0] = bv0.x; Bs[nxt][kq + 1][r0] = bv0.y;
            Bs[nxt][kq + 2][r0] = bv0.z; Bs[nxt][kq + 3][r0] = bv0.w;
            Bs[nxt][kq + 0][r1] = bv1.x; Bs[nxt][kq + 1][r1] = bv1.y;
            Bs[nxt][kq + 2][r1] = bv1.z; Bs[nxt][kq + 3][r1] = bv1.w;
        }
        __syncthreads();
    }

    // ---------------- fused epilogue: bias + LIF scan -----------------------
    float bb[8];
    {
        const float* bp = bias + colBase + bCol;
        float4 q0 = *(const float4*)(bp + 0);
        float4 q1 = *(const float4*)(bp + 4);
        bb[0] = q0.x; bb[1] = q0.y; bb[2] = q0.z; bb[3] = q0.w;
        bb[4] = q1.x; bb[5] = q1.y; bb[6] = q1.z; bb[7] = q1.w;
    }

    // reuse As+Bs (contiguous 33792 B) as Cs[64][STR]
    float* Cs = &As[0][0][0];

#pragma unroll 1
    for (int half = 0; half < 2; half++) {
        // warps with wm == half own rows [64*half, 64*half+64): stage them
        if (wm == half) {
            const int rloc = lr * 8;
#pragma unroll
            for (int i = 0; i < 8; i++) {
                float* cp = Cs + (rloc + i) * STR + bCol;
                float4 v0, v1;
                v0.x = acc[i][0] + bb[0];
                v0.y = acc[i][1] + bb[1];
                v0.z = acc[i][2] + bb[2];
                v0.w = acc[i][3] + bb[3];
                v1.x = acc[i][4] + bb[4];
                v1.y = acc[i][5] + bb[5];
                v1.z = acc[i][6] + bb[6];
                v1.w = acc[i][7] + bb[7];
                *(float4*)(cp + 0) = v0;
                *(float4*)(cp + 4) = v1;
            }
        }
        __syncthreads();

        // 256 threads: 2 b-chunks x 128 columns, one LIF scan each
        {
            const int blocal = tid >> 7;          // 0..1
            const int col    = tid & 127;         // 0..127
            const int bG     = blockIdx.y * 4 + half * 2 + blocal;
            float* ob = out + (size_t)bG * H_DIM + colBase + col;
            const float* cs = Cs + (blocal * 32) * STR + col;
            float v = 0.0f, cnt = 0.0f;
#pragma unroll
            for (int t = 0; t < T_STEPS; t++) {
                float x = cs[t * STR];
                v = __fadd_rn(v, __fmul_rn(__fsub_rn(x, v), 0.5f));
                bool fire = (v >= 1.0f);
                float s = fire ? 1.0f : 0.0f;
                ob[(size_t)t * BH] = s;
                cnt += s;
                v = fire ? 0.0f : v;
            }
            ob[(size_t)T_STEPS * BH] = cnt;       // count block after spk_seq
        }
        __syncthreads();
    }
}

// ---------------------------------------------------------------- launch
extern "C" void kernel_launch(void* const* d_in, const int* in_sizes, int n_in,
                              void* d_out, int out_size)
{
    const float* x_seq = (const float*)d_in[0];  // [T,B,F]
    const float* W     = (const float*)d_in[1];  // [H,F]
    const float* b     = (const float*)d_in[2];  // [H]
    float* out = (float*)d_out;

    dim3 gg(N_DIM / BN, M_DIM / BM);   // (32, 64)
    gemm_lif_fused<<<gg, 256>>>(x_seq, W, b, out);
}